// round 15
// baseline (speedup 1.0000x reference)
#include <cuda_runtime.h>
#include <cuda_fp16.h>
#include <cstdint>

#define BV 8
#define TV 512
#define DV 2048
#define HV 2048
#define STEPS (BV * TV)
#define R4H (4 * HV)
#define GRID 148
#define JPC 14
#define ROWS 56
#define NTH 256
// LSTM smem: W it2,3 only (56 rows x 1024 halves = 114688 B) + pre_part[2][56]
#define SM23_U4 (ROWS * 128)
#define LSTM_SMEM (SM23_U4 * 16 + 2 * ROWS * 4)
#define OUTSTRIDE ((size_t)STEPS * HV)

__device__ float g_xp[(size_t)STEPS * R4H];
__device__ __align__(16) __half g_hh[2][HV];
__device__ unsigned int g_bar;

__device__ __forceinline__ __half2 u2h(unsigned u) {
    return *reinterpret_cast<__half2*>(&u);
}
__device__ __forceinline__ uint4 pack8(float4 f0, float4 f1) {
    uint4 v; __half2 h;
    h = __floats2half2_rn(f0.x, f0.y); v.x = *(unsigned*)&h;
    h = __floats2half2_rn(f0.z, f0.w); v.y = *(unsigned*)&h;
    h = __floats2half2_rn(f1.x, f1.y); v.z = *(unsigned*)&h;
    h = __floats2half2_rn(f1.z, f1.w); v.w = *(unsigned*)&h;
    return v;
}
__device__ __forceinline__ uint32_t smem_u32(const void* p) {
    uint32_t a;
    asm("{ .reg .u64 t; cvta.to.shared.u64 t, %1; cvt.u32.u64 %0, t; }"
        : "=r"(a) : "l"(p));
    return a;
}
__device__ __forceinline__ void ldm_x4(uint32_t& r0, uint32_t& r1,
                                       uint32_t& r2, uint32_t& r3, uint32_t addr) {
    asm volatile("ldmatrix.sync.aligned.m8n8.x4.shared.b16 {%0,%1,%2,%3}, [%4];"
                 : "=r"(r0), "=r"(r1), "=r"(r2), "=r"(r3) : "r"(addr));
}
__device__ __forceinline__ void mma16816(float* c, const uint32_t* a,
                                         uint32_t b0, uint32_t b1) {
    asm volatile(
        "mma.sync.aligned.m16n8k16.row.col.f32.f16.f16.f32 "
        "{%0,%1,%2,%3}, {%4,%5,%6,%7}, {%8,%9}, {%0,%1,%2,%3};"
        : "+f"(c[0]), "+f"(c[1]), "+f"(c[2]), "+f"(c[3])
        : "r"(a[0]), "r"(a[1]), "r"(a[2]), "r"(a[3]), "r"(b0), "r"(b1));
}

// ---------------------------------------------------------------- GEMM (HMMA, +init) — R12 verbatim
__global__ void __launch_bounds__(256)
gemm_xp(const float* __restrict__ A, const float* __restrict__ Bm,
        const float* __restrict__ bias, const float* __restrict__ h0) {
    __shared__ __align__(16) __half A_s[128 * 40];
    __shared__ __align__(16) __half B_s[128 * 40];
    const int tid = threadIdx.x;

    if (blockIdx.x == 0 && blockIdx.y == 0) {
        if (tid == 0) g_bar = 0u;
        for (int i = tid; i < HV; i += 256) g_hh[0][i] = __float2half(h0[i]);
    }

    const int m0 = blockIdx.x * 128, n0 = blockIdx.y * 128;
    const int warp = tid >> 5, lane = tid & 31;
    const int nrow = (warp & 3) * 32, mcol = (warp >> 2) * 64;
    const int sr = tid >> 1, sc = (tid & 1) * 16;
    const float* Ald = A + (size_t)(n0 + sr) * DV + sc;
    const float* Bld = Bm + (size_t)(m0 + sr) * DV + sc;

    const int mat = lane >> 3, r8 = lane & 7;
    const int mrow = (mat & 1) * 8 + r8;
    const int mck = (mat >> 1) * 8;
    const uint32_t aBase = smem_u32(A_s), bBase = smem_u32(B_s);

    float c[2][8][4];
#pragma unroll
    for (int mt = 0; mt < 2; ++mt)
#pragma unroll
        for (int nt = 0; nt < 8; ++nt)
#pragma unroll
            for (int q = 0; q < 4; ++q) c[mt][nt][q] = 0.f;

    float4 pa[4], pb[4];
#pragma unroll
    for (int i = 0; i < 4; ++i) {
        pa[i] = *(const float4*)(Ald + 4 * i);
        pb[i] = *(const float4*)(Bld + 4 * i);
    }

    const int NKT = DV / 32;
    for (int kt = 0; kt < NKT; ++kt) {
        __syncthreads();
        {
            uint4 u0 = pack8(pa[0], pa[1]), u1 = pack8(pa[2], pa[3]);
            *(uint4*)&A_s[sr * 40 + sc] = u0;
            *(uint4*)&A_s[sr * 40 + sc + 8] = u1;
            uint4 v0 = pack8(pb[0], pb[1]), v1 = pack8(pb[2], pb[3]);
            *(uint4*)&B_s[sr * 40 + sc] = v0;
            *(uint4*)&B_s[sr * 40 + sc + 8] = v1;
        }
        __syncthreads();
        if (kt + 1 < NKT) {
            const float* An = Ald + (kt + 1) * 32;
            const float* Bn = Bld + (kt + 1) * 32;
#pragma unroll
            for (int i = 0; i < 4; ++i) {
                pa[i] = *(const float4*)(An + 4 * i);
                pb[i] = *(const float4*)(Bn + 4 * i);
            }
        }
#pragma unroll
        for (int ks = 0; ks < 2; ++ks) {
            const int k0 = ks * 16;
            uint32_t a[2][4];
#pragma unroll
            for (int mt = 0; mt < 2; ++mt) {
                uint32_t ad = aBase +
                    (uint32_t)(((nrow + mt * 16 + mrow) * 40 + k0 + mck) * 2);
                ldm_x4(a[mt][0], a[mt][1], a[mt][2], a[mt][3], ad);
            }
            uint32_t b[8][2];
#pragma unroll
            for (int bt = 0; bt < 4; ++bt) {
                uint32_t r0, r1, r2, r3;
                uint32_t bd = bBase +
                    (uint32_t)(((mcol + bt * 16 + mrow) * 40 + k0 + mck) * 2);
                ldm_x4(r0, r1, r2, r3, bd);
                b[2 * bt][0] = r0; b[2 * bt + 1][0] = r1;
                b[2 * bt][1] = r2; b[2 * bt + 1][1] = r3;
            }
#pragma unroll
            for (int mt = 0; mt < 2; ++mt)
#pragma unroll
                for (int nt = 0; nt < 8; ++nt)
                    mma16816(c[mt][nt], a[mt], b[nt][0], b[nt][1]);
        }
    }

#pragma unroll
    for (int mt = 0; mt < 2; ++mt) {
        const int n = n0 + nrow + mt * 16 + (lane >> 2);
#pragma unroll
        for (int nt = 0; nt < 8; ++nt) {
            const int m = m0 + mcol + nt * 8 + (lane & 3) * 2;
            float2 bb = *(const float2*)(bias + m);
            float* cp = g_xp + (size_t)n * R4H + m;
            float2 o0, o1;
            o0.x = c[mt][nt][0] + bb.x; o0.y = c[mt][nt][1] + bb.y;
            o1.x = c[mt][nt][2] + bb.x; o1.y = c[mt][nt][3] + bb.y;
            *(float2*)cp = o0;
            *(float2*)(cp + (size_t)8 * R4H) = o1;
        }
    }
}

// ---------------------------------------------------------------- LSTM
// R12/R5 structure; ONLY change: W it0,1 cached in registers (loaded once from
// global), it2,3 streamed from SMEM. Accumulation order per row identical.
__global__ void __launch_bounds__(NTH, 1)
lstm_kernel(const float* __restrict__ c0, const float* __restrict__ W_hh,
            const float* __restrict__ b_hh, float* __restrict__ out) {
    extern __shared__ __align__(16) unsigned char smem_raw[];
    uint4* SM23 = reinterpret_cast<uint4*>(smem_raw);
    float* pre_part = reinterpret_cast<float*>(smem_raw + SM23_U4 * 16);

    const int tid = threadIdx.x, cta = blockIdx.x;
    const int j0 = cta * JPC;
    int J = HV - j0; if (J > JPC) J = JPC; if (J < 0) J = 0;

    // ---- stage W it2,3 -> SMEM fp16 (once). Row rl: [khalf][it-2][lane] uint4
    for (int u = tid; u < SM23_U4; u += NTH) {
        int rl = u >> 7, rem = u & 127;
        int kh = rem >> 6, it2 = (rem >> 5) & 1, ln8 = rem & 31;
        int jl = rl >> 2, gate = rl & 3;
        uint4 v = make_uint4(0, 0, 0, 0);
        if (jl < J) {
            const float* wp = W_hh + ((size_t)gate * HV + j0 + jl) * HV
                              + kh * 1024 + (2 + it2) * 256 + ln8 * 8;
            v = pack8(*(const float4*)wp, *(const float4*)(wp + 4));
        }
        SM23[u] = v;
    }

    const int warp = tid >> 5, lane = tid & 31;
    const int grp = warp >> 1, khalf = warp & 1;
    const int kb = khalf << 10;
    const int rbase = grp * JPC;

    // ---- W it0,1 -> registers (once, from global with fp16 pack)
    uint4 wr0[JPC], wr1[JPC];
#pragma unroll
    for (int r = 0; r < JPC; ++r) {
        int rl = rbase + r, jl = rl >> 2, gate = rl & 3;
        uint4 v0 = make_uint4(0, 0, 0, 0), v1 = v0;
        if (jl < J) {
            const float* wp = W_hh + ((size_t)gate * HV + j0 + jl) * HV + kb + lane * 8;
            v0 = pack8(*(const float4*)wp, *(const float4*)(wp + 4));
            v1 = pack8(*(const float4*)(wp + 256), *(const float4*)(wp + 260));
        }
        wr0[r] = v0; wr1[r] = v1;
    }

    float c_val = 0.f, b_r[4] = {0.f, 0.f, 0.f, 0.f};
    if (tid < J) {
        c_val = c0[j0 + tid];
#pragma unroll
        for (int g = 0; g < 4; ++g) b_r[g] = b_hh[g * HV + j0 + tid];
    }
    float xp_r[4] = {0.f, 0.f, 0.f, 0.f};
    if (tid < J) {
#pragma unroll
        for (int g = 0; g < 4; ++g)
            xp_r[g] = __ldcg(&g_xp[(size_t)g * HV + j0 + tid]);
    }
    __syncthreads();

    const int smbase = rbase * 128 + khalf * 64 + lane;   // uint4 idx into SM23
    volatile unsigned int* barp = &g_bar;

    for (int t = 0; t < STEPS; ++t) {
        const int p = t & 1;

        // ---- h (fp16) -> registers: 4x LDG.128 (L2)
        uint4 hq[4];
        {
            const uint4* hb4 = reinterpret_cast<const uint4*>(&g_hh[p][kb]) + lane;
#pragma unroll
            for (int it = 0; it < 4; ++it) hq[it] = __ldcg(hb4 + it * 32);
        }

        // ---- 14 rows: it0,1 from regs, it2,3 from SMEM; same 4-stream order
#pragma unroll
        for (int r = 0; r < JPC; ++r) {
            uint4 w2 = SM23[smbase + r * 128];
            uint4 w3 = SM23[smbase + r * 128 + 32];
            __half2 a0, a1, a2, a3;
            a0 = __hmul2(u2h(wr0[r].x), u2h(hq[0].x));
            a1 = __hmul2(u2h(wr0[r].y), u2h(hq[0].y));
            a2 = __hmul2(u2h(wr0[r].z), u2h(hq[0].z));
            a3 = __hmul2(u2h(wr0[r].w), u2h(hq[0].w));
            a0 = __hfma2(u2h(wr1[r].x), u2h(hq[1].x), a0);
            a1 = __hfma2(u2h(wr1[r].y), u2h(hq[1].y), a1);
            a2 = __hfma2(u2h(wr1[r].z), u2h(hq[1].z), a2);
            a3 = __hfma2(u2h(wr1[r].w), u2h(hq[1].w), a3);
            a0 = __hfma2(u2h(w2.x), u2h(hq[2].x), a0);
            a1 = __hfma2(u2h(w2.y), u2h(hq[2].y), a1);
            a2 = __hfma2(u2h(w2.z), u2h(hq[2].z), a2);
            a3 = __hfma2(u2h(w2.w), u2h(hq[2].w), a3);
            a0 = __hfma2(u2h(w3.x), u2h(hq[3].x), a0);
            a1 = __hfma2(u2h(w3.y), u2h(hq[3].y), a1);
            a2 = __hfma2(u2h(w3.z), u2h(hq[3].z), a2);
            a3 = __hfma2(u2h(w3.w), u2h(hq[3].w), a3);
            float2 f0 = __half22float2(a0);
            float2 f1 = __half22float2(a1);
            float2 f2 = __half22float2(a2);
            float2 f3 = __half22float2(a3);
            float v = ((f0.x + f0.y) + (f1.x + f1.y)) +
                      ((f2.x + f2.y) + (f3.x + f3.y));
            v += __shfl_xor_sync(~0u, v, 16);
            v += __shfl_xor_sync(~0u, v, 8);
            v += __shfl_xor_sync(~0u, v, 4);
            v += __shfl_xor_sync(~0u, v, 2);
            v += __shfl_xor_sync(~0u, v, 1);
            if (lane == 0) pre_part[khalf * ROWS + rbase + r] = v;
        }
        __syncthreads();   // #1: pre_part ready

        if (tid < J) {
            const int rl = tid << 2;
            float pi = xp_r[0] + b_r[0] + pre_part[rl + 0] + pre_part[ROWS + rl + 0];
            float pf = xp_r[1] + b_r[1] + pre_part[rl + 1] + pre_part[ROWS + rl + 1];
            float po = xp_r[2] + b_r[2] + pre_part[rl + 2] + pre_part[ROWS + rl + 2];
            float pg = xp_r[3] + b_r[3] + pre_part[rl + 3] + pre_part[ROWS + rl + 3];
            float i_t = __fdividef(1.0f, 1.0f + __expf(-pi));
            float f_t = __fdividef(1.0f, 1.0f + __expf(-pf));
            float o_t = __fdividef(1.0f, 1.0f + __expf(-po));
            float g_t = __fdividef(2.0f, 1.0f + __expf(-2.0f * pg)) - 1.0f;
            c_val = c_val * f_t + i_t * g_t;
            float tc = __fdividef(2.0f, 1.0f + __expf(-2.0f * c_val)) - 1.0f;
            float h_n = o_t * tc;
            g_hh[p ^ 1][j0 + tid] = __float2half(h_n);
            size_t oi = (size_t)t * HV + j0 + tid;
            out[oi] = h_n;
            out[OUTSTRIDE + oi] = f_t;
            out[2 * OUTSTRIDE + oi] = i_t;
        }

        __syncthreads();
        if (tid == 0) {
            __threadfence();
            atomicAdd(&g_bar, 1u);
        }
        if (t + 1 < STEPS && tid < J) {
#pragma unroll
            for (int g = 0; g < 4; ++g)
                xp_r[g] = __ldcg(&g_xp[(size_t)(t + 1) * R4H + g * HV + j0 + tid]);
        }
        if (tid == 0) {
            const unsigned tgt = (unsigned)(t + 1) * GRID;
            while (*barp < tgt) {}
            __threadfence();
        }
        __syncthreads();
    }
}

extern "C" void kernel_launch(void* const* d_in, const int* in_sizes, int n_in,
                              void* d_out, int out_size) {
    const float* input_ = (const float*)d_in[0];
    const float* h0 = (const float*)d_in[1];
    const float* c0 = (const float*)d_in[2];
    const float* W_ih = (const float*)d_in[3];
    const float* b_ih = (const float*)d_in[4];
    const float* W_hh = (const float*)d_in[5];
    const float* b_hh = (const float*)d_in[6];
    float* out = (float*)d_out;

    static int smem_set = 0;
    if (!smem_set) {
        cudaFuncSetAttribute(lstm_kernel, cudaFuncAttributeMaxDynamicSharedMemorySize,
                             LSTM_SMEM);
        smem_set = 1;
    }

    gemm_xp<<<dim3(R4H / 128, STEPS / 128), 256>>>(input_, W_ih, b_ih, h0);
    lstm_kernel<<<GRID, NTH, LSTM_SMEM>>>(c0, W_hh, b_hh, out);
}

// round 16
// speedup vs baseline: 1.2554x; 1.2554x over previous
#include <cuda_runtime.h>
#include <cuda_fp16.h>
#include <cstdint>

#define BV 8
#define TV 512
#define DV 2048
#define HV 2048
#define STEPS (BV * TV)
#define R4H (4 * HV)
#define GRID 296                   /* 2 CTAs per SM */
#define JPC 7                      /* hidden units per CTA */
#define ROWS 28                    /* 4*JPC gate-rows per CTA */
#define NTH 256
#define LSTM_SMEM (ROWS * HV * 2 + 2 * ROWS * 4)   /* 114912 B */
#define OUTSTRIDE ((size_t)STEPS * HV)

__device__ float g_xp[(size_t)STEPS * R4H];
__device__ __align__(16) __half g_hh[2][HV];
__device__ unsigned int g_bar;

__device__ __forceinline__ __half2 u2h(unsigned u) {
    return *reinterpret_cast<__half2*>(&u);
}
__device__ __forceinline__ uint4 pack8(float4 f0, float4 f1) {
    uint4 v; __half2 h;
    h = __floats2half2_rn(f0.x, f0.y); v.x = *(unsigned*)&h;
    h = __floats2half2_rn(f0.z, f0.w); v.y = *(unsigned*)&h;
    h = __floats2half2_rn(f1.x, f1.y); v.z = *(unsigned*)&h;
    h = __floats2half2_rn(f1.z, f1.w); v.w = *(unsigned*)&h;
    return v;
}
__device__ __forceinline__ uint32_t smem_u32(const void* p) {
    uint32_t a;
    asm("{ .reg .u64 t; cvta.to.shared.u64 t, %1; cvt.u32.u64 %0, t; }"
        : "=r"(a) : "l"(p));
    return a;
}
__device__ __forceinline__ void ldm_x4(uint32_t& r0, uint32_t& r1,
                                       uint32_t& r2, uint32_t& r3, uint32_t addr) {
    asm volatile("ldmatrix.sync.aligned.m8n8.x4.shared.b16 {%0,%1,%2,%3}, [%4];"
                 : "=r"(r0), "=r"(r1), "=r"(r2), "=r"(r3) : "r"(addr));
}
__device__ __forceinline__ void mma16816(float* c, const uint32_t* a,
                                         uint32_t b0, uint32_t b1) {
    asm volatile(
        "mma.sync.aligned.m16n8k16.row.col.f32.f16.f16.f32 "
        "{%0,%1,%2,%3}, {%4,%5,%6,%7}, {%8,%9}, {%0,%1,%2,%3};"
        : "+f"(c[0]), "+f"(c[1]), "+f"(c[2]), "+f"(c[3])
        : "r"(a[0]), "r"(a[1]), "r"(a[2]), "r"(a[3]), "r"(b0), "r"(b1));
}

// ---------------------------------------------------------------- GEMM (HMMA, +init) — R12 verbatim
__global__ void __launch_bounds__(256)
gemm_xp(const float* __restrict__ A, const float* __restrict__ Bm,
        const float* __restrict__ bias, const float* __restrict__ h0) {
    __shared__ __align__(16) __half A_s[128 * 40];
    __shared__ __align__(16) __half B_s[128 * 40];
    const int tid = threadIdx.x;

    if (blockIdx.x == 0 && blockIdx.y == 0) {
        if (tid == 0) g_bar = 0u;
        for (int i = tid; i < HV; i += 256) g_hh[0][i] = __float2half(h0[i]);
    }

    const int m0 = blockIdx.x * 128, n0 = blockIdx.y * 128;
    const int warp = tid >> 5, lane = tid & 31;
    const int nrow = (warp & 3) * 32, mcol = (warp >> 2) * 64;
    const int sr = tid >> 1, sc = (tid & 1) * 16;
    const float* Ald = A + (size_t)(n0 + sr) * DV + sc;
    const float* Bld = Bm + (size_t)(m0 + sr) * DV + sc;

    const int mat = lane >> 3, r8 = lane & 7;
    const int mrow = (mat & 1) * 8 + r8;
    const int mck = (mat >> 1) * 8;
    const uint32_t aBase = smem_u32(A_s), bBase = smem_u32(B_s);

    float c[2][8][4];
#pragma unroll
    for (int mt = 0; mt < 2; ++mt)
#pragma unroll
        for (int nt = 0; nt < 8; ++nt)
#pragma unroll
            for (int q = 0; q < 4; ++q) c[mt][nt][q] = 0.f;

    float4 pa[4], pb[4];
#pragma unroll
    for (int i = 0; i < 4; ++i) {
        pa[i] = *(const float4*)(Ald + 4 * i);
        pb[i] = *(const float4*)(Bld + 4 * i);
    }

    const int NKT = DV / 32;
    for (int kt = 0; kt < NKT; ++kt) {
        __syncthreads();
        {
            uint4 u0 = pack8(pa[0], pa[1]), u1 = pack8(pa[2], pa[3]);
            *(uint4*)&A_s[sr * 40 + sc] = u0;
            *(uint4*)&A_s[sr * 40 + sc + 8] = u1;
            uint4 v0 = pack8(pb[0], pb[1]), v1 = pack8(pb[2], pb[3]);
            *(uint4*)&B_s[sr * 40 + sc] = v0;
            *(uint4*)&B_s[sr * 40 + sc + 8] = v1;
        }
        __syncthreads();
        if (kt + 1 < NKT) {
            const float* An = Ald + (kt + 1) * 32;
            const float* Bn = Bld + (kt + 1) * 32;
#pragma unroll
            for (int i = 0; i < 4; ++i) {
                pa[i] = *(const float4*)(An + 4 * i);
                pb[i] = *(const float4*)(Bn + 4 * i);
            }
        }
#pragma unroll
        for (int ks = 0; ks < 2; ++ks) {
            const int k0 = ks * 16;
            uint32_t a[2][4];
#pragma unroll
            for (int mt = 0; mt < 2; ++mt) {
                uint32_t ad = aBase +
                    (uint32_t)(((nrow + mt * 16 + mrow) * 40 + k0 + mck) * 2);
                ldm_x4(a[mt][0], a[mt][1], a[mt][2], a[mt][3], ad);
            }
            uint32_t b[8][2];
#pragma unroll
            for (int bt = 0; bt < 4; ++bt) {
                uint32_t r0, r1, r2, r3;
                uint32_t bd = bBase +
                    (uint32_t)(((mcol + bt * 16 + mrow) * 40 + k0 + mck) * 2);
                ldm_x4(r0, r1, r2, r3, bd);
                b[2 * bt][0] = r0; b[2 * bt + 1][0] = r1;
                b[2 * bt][1] = r2; b[2 * bt + 1][1] = r3;
            }
#pragma unroll
            for (int mt = 0; mt < 2; ++mt)
#pragma unroll
                for (int nt = 0; nt < 8; ++nt)
                    mma16816(c[mt][nt], a[mt], b[nt][0], b[nt][1]);
        }
    }

#pragma unroll
    for (int mt = 0; mt < 2; ++mt) {
        const int n = n0 + nrow + mt * 16 + (lane >> 2);
#pragma unroll
        for (int nt = 0; nt < 8; ++nt) {
            const int m = m0 + mcol + nt * 8 + (lane & 3) * 2;
            float2 bb = *(const float2*)(bias + m);
            float* cp = g_xp + (size_t)n * R4H + m;
            float2 o0, o1;
            o0.x = c[mt][nt][0] + bb.x; o0.y = c[mt][nt][1] + bb.y;
            o1.x = c[mt][nt][2] + bb.x; o1.y = c[mt][nt][3] + bb.y;
            *(float2*)cp = o0;
            *(float2*)(cp + (size_t)8 * R4H) = o1;
        }
    }
}

// ---------------------------------------------------------------- LSTM
// R12/R5 inner loop verbatim; 2 CTAs per SM (GRID=296, JPC=7, ROWS=28).
__global__ void __launch_bounds__(NTH, 2)
lstm_kernel(const float* __restrict__ c0, const float* __restrict__ W_hh,
            const float* __restrict__ b_hh, float* __restrict__ out) {
    extern __shared__ __align__(16) unsigned char smem_raw[];
    uint4* Wq = reinterpret_cast<uint4*>(smem_raw);
    float* pre_part = reinterpret_cast<float*>(smem_raw + (size_t)ROWS * HV * 2);

    const int tid = threadIdx.x, cta = blockIdx.x;
    const int j0 = cta * JPC;
    int J = HV - j0; if (J > JPC) J = JPC; if (J < 0) J = 0;

    // stage W_hh slice -> SMEM fp16, vectorized (uint4 = 8 halves)
    for (int u = tid; u < ROWS * 256; u += NTH) {
        int rl = u >> 8, rem = u & 255;
        int jl = rl >> 2, gate = rl & 3;
        uint4 v = make_uint4(0, 0, 0, 0);
        if (jl < J) {
            const float* wp = W_hh + ((size_t)gate * HV + j0 + jl) * HV + rem * 8;
            v = pack8(*(const float4*)wp, *(const float4*)(wp + 4));
        }
        Wq[u] = v;
    }

    const int warp = tid >> 5, lane = tid & 31;
    const int grp = warp >> 1, khalf = warp & 1;
    const int kb = khalf << 10;
    const int rbase = grp * JPC;

    float c_val = 0.f, b_r[4] = {0.f, 0.f, 0.f, 0.f};
    if (tid < J) {
        c_val = c0[j0 + tid];
#pragma unroll
        for (int g = 0; g < 4; ++g) b_r[g] = b_hh[g * HV + j0 + tid];
    }
    float xp_r[4] = {0.f, 0.f, 0.f, 0.f};
    if (tid < J) {
#pragma unroll
        for (int g = 0; g < 4; ++g)
            xp_r[g] = __ldcg(&g_xp[(size_t)g * HV + j0 + tid]);
    }
    __syncthreads();

    const size_t wbase = (size_t)rbase * 256 + (size_t)khalf * 128 + lane;
    volatile unsigned int* barp = &g_bar;
    const __half2 hz = __float2half2_rn(0.f);

    for (int t = 0; t < STEPS; ++t) {
        const int p = t & 1;

        uint4 hq[4];
        {
            const uint4* hb4 = reinterpret_cast<const uint4*>(&g_hh[p][kb]) + lane;
#pragma unroll
            for (int it = 0; it < 4; ++it) hq[it] = __ldcg(hb4 + it * 32);
        }

        __half2 acc[JPC][4];
#pragma unroll
        for (int r = 0; r < JPC; ++r)
#pragma unroll
            for (int s = 0; s < 4; ++s) acc[r][s] = hz;

#pragma unroll
        for (int it = 0; it < 4; ++it) {
#pragma unroll
            for (int r = 0; r < JPC; ++r) {
                uint4 w = Wq[wbase + (size_t)r * 256 + it * 32];
                acc[r][0] = __hfma2(u2h(w.x), u2h(hq[it].x), acc[r][0]);
                acc[r][1] = __hfma2(u2h(w.y), u2h(hq[it].y), acc[r][1]);
                acc[r][2] = __hfma2(u2h(w.z), u2h(hq[it].z), acc[r][2]);
                acc[r][3] = __hfma2(u2h(w.w), u2h(hq[it].w), acc[r][3]);
            }
        }
#pragma unroll
        for (int r = 0; r < JPC; ++r) {
            float2 f0 = __half22float2(acc[r][0]);
            float2 f1 = __half22float2(acc[r][1]);
            float2 f2 = __half22float2(acc[r][2]);
            float2 f3 = __half22float2(acc[r][3]);
            float v = ((f0.x + f0.y) + (f1.x + f1.y)) +
                      ((f2.x + f2.y) + (f3.x + f3.y));
            v += __shfl_xor_sync(~0u, v, 16);
            v += __shfl_xor_sync(~0u, v, 8);
            v += __shfl_xor_sync(~0u, v, 4);
            v += __shfl_xor_sync(~0u, v, 2);
            v += __shfl_xor_sync(~0u, v, 1);
            if (lane == 0) pre_part[khalf * ROWS + rbase + r] = v;
        }
        __syncthreads();

        if (tid < J) {
            const int rl = tid << 2;
            float pi = xp_r[0] + b_r[0] + pre_part[rl + 0] + pre_part[ROWS + rl + 0];
            float pf = xp_r[1] + b_r[1] + pre_part[rl + 1] + pre_part[ROWS + rl + 1];
            float po = xp_r[2] + b_r[2] + pre_part[rl + 2] + pre_part[ROWS + rl + 2];
            float pg = xp_r[3] + b_r[3] + pre_part[rl + 3] + pre_part[ROWS + rl + 3];
            float i_t = __fdividef(1.0f, 1.0f + __expf(-pi));
            float f_t = __fdividef(1.0f, 1.0f + __expf(-pf));
            float o_t = __fdividef(1.0f, 1.0f + __expf(-po));
            float g_t = __fdividef(2.0f, 1.0f + __expf(-2.0f * pg)) - 1.0f;
            c_val = c_val * f_t + i_t * g_t;
            float tc = __fdividef(2.0f, 1.0f + __expf(-2.0f * c_val)) - 1.0f;
            float h_n = o_t * tc;
            g_hh[p ^ 1][j0 + tid] = __float2half(h_n);
            size_t oi = (size_t)t * HV + j0 + tid;
            out[oi] = h_n;
            out[OUTSTRIDE + oi] = f_t;
            out[2 * OUTSTRIDE + oi] = i_t;
        }

        __syncthreads();
        if (tid == 0) {
            __threadfence();
            atomicAdd(&g_bar, 1u);
        }
        if (t + 1 < STEPS && tid < J) {
#pragma unroll
            for (int g = 0; g < 4; ++g)
                xp_r[g] = __ldcg(&g_xp[(size_t)(t + 1) * R4H + g * HV + j0 + tid]);
        }
        if (tid == 0) {
            const unsigned tgt = (unsigned)(t + 1) * GRID;
            while (*barp < tgt) {}
            __threadfence();
        }
        __syncthreads();
    }
}

extern "C" void kernel_launch(void* const* d_in, const int* in_sizes, int n_in,
                              void* d_out, int out_size) {
    const float* input_ = (const float*)d_in[0];
    const float* h0 = (const float*)d_in[1];
    const float* c0 = (const float*)d_in[2];
    const float* W_ih = (const float*)d_in[3];
    const float* b_ih = (const float*)d_in[4];
    const float* W_hh = (const float*)d_in[5];
    const float* b_hh = (const float*)d_in[6];
    float* out = (float*)d_out;

    static int smem_set = 0;
    if (!smem_set) {
        cudaFuncSetAttribute(lstm_kernel, cudaFuncAttributeMaxDynamicSharedMemorySize,
                             LSTM_SMEM);
        smem_set = 1;
    }

    gemm_xp<<<dim3(R4H / 128, STEPS / 128), 256>>>(input_, W_ih, b_ih, h0);
    lstm_kernel<<<GRID, NTH, LSTM_SMEM>>>(c0, W_hh, b_hh, out);
}

// round 17
// speedup vs baseline: 1.2605x; 1.0040x over previous
#include <cuda_runtime.h>
#include <cuda_fp16.h>
#include <cstdint>

#define BV 8
#define TV 512
#define DV 2048
#define HV 2048
#define STEPS (BV * TV)
#define R4H (4 * HV)
#define GRID 296                   /* 2 CTAs per SM */
#define JPC 7                      /* hidden units per CTA */
#define ROWS 28                    /* 4*JPC gate-rows per CTA */
#define NTH 256
#define LSTM_SMEM (ROWS * HV * 2 + 2 * ROWS * 4)   /* 114912 B */
#define OUTSTRIDE ((size_t)STEPS * HV)

__device__ float g_xp[(size_t)STEPS * R4H];
__device__ __align__(16) __half g_hh[2][HV];
__device__ unsigned int g_bar;

__device__ __forceinline__ __half2 u2h(unsigned u) {
    return *reinterpret_cast<__half2*>(&u);
}
__device__ __forceinline__ uint4 pack8(float4 f0, float4 f1) {
    uint4 v; __half2 h;
    h = __floats2half2_rn(f0.x, f0.y); v.x = *(unsigned*)&h;
    h = __floats2half2_rn(f0.z, f0.w); v.y = *(unsigned*)&h;
    h = __floats2half2_rn(f1.x, f1.y); v.z = *(unsigned*)&h;
    h = __floats2half2_rn(f1.z, f1.w); v.w = *(unsigned*)&h;
    return v;
}
__device__ __forceinline__ uint32_t smem_u32(const void* p) {
    uint32_t a;
    asm("{ .reg .u64 t; cvta.to.shared.u64 t, %1; cvt.u32.u64 %0, t; }"
        : "=r"(a) : "l"(p));
    return a;
}
__device__ __forceinline__ void ldm_x4(uint32_t& r0, uint32_t& r1,
                                       uint32_t& r2, uint32_t& r3, uint32_t addr) {
    asm volatile("ldmatrix.sync.aligned.m8n8.x4.shared.b16 {%0,%1,%2,%3}, [%4];"
                 : "=r"(r0), "=r"(r1), "=r"(r2), "=r"(r3) : "r"(addr));
}
__device__ __forceinline__ void mma16816(float* c, const uint32_t* a,
                                         uint32_t b0, uint32_t b1) {
    asm volatile(
        "mma.sync.aligned.m16n8k16.row.col.f32.f16.f16.f32 "
        "{%0,%1,%2,%3}, {%4,%5,%6,%7}, {%8,%9}, {%0,%1,%2,%3};"
        : "+f"(c[0]), "+f"(c[1]), "+f"(c[2]), "+f"(c[3])
        : "r"(a[0]), "r"(a[1]), "r"(a[2]), "r"(a[3]), "r"(b0), "r"(b1));
}

// ---------------------------------------------------------------- GEMM (HMMA, +init) — R12 verbatim
__global__ void __launch_bounds__(256)
gemm_xp(const float* __restrict__ A, const float* __restrict__ Bm,
        const float* __restrict__ bias, const float* __restrict__ h0) {
    __shared__ __align__(16) __half A_s[128 * 40];
    __shared__ __align__(16) __half B_s[128 * 40];
    const int tid = threadIdx.x;

    if (blockIdx.x == 0 && blockIdx.y == 0) {
        if (tid == 0) g_bar = 0u;
        for (int i = tid; i < HV; i += 256) g_hh[0][i] = __float2half(h0[i]);
    }

    const int m0 = blockIdx.x * 128, n0 = blockIdx.y * 128;
    const int warp = tid >> 5, lane = tid & 31;
    const int nrow = (warp & 3) * 32, mcol = (warp >> 2) * 64;
    const int sr = tid >> 1, sc = (tid & 1) * 16;
    const float* Ald = A + (size_t)(n0 + sr) * DV + sc;
    const float* Bld = Bm + (size_t)(m0 + sr) * DV + sc;

    const int mat = lane >> 3, r8 = lane & 7;
    const int mrow = (mat & 1) * 8 + r8;
    const int mck = (mat >> 1) * 8;
    const uint32_t aBase = smem_u32(A_s), bBase = smem_u32(B_s);

    float c[2][8][4];
#pragma unroll
    for (int mt = 0; mt < 2; ++mt)
#pragma unroll
        for (int nt = 0; nt < 8; ++nt)
#pragma unroll
            for (int q = 0; q < 4; ++q) c[mt][nt][q] = 0.f;

    float4 pa[4], pb[4];
#pragma unroll
    for (int i = 0; i < 4; ++i) {
        pa[i] = *(const float4*)(Ald + 4 * i);
        pb[i] = *(const float4*)(Bld + 4 * i);
    }

    const int NKT = DV / 32;
    for (int kt = 0; kt < NKT; ++kt) {
        __syncthreads();
        {
            uint4 u0 = pack8(pa[0], pa[1]), u1 = pack8(pa[2], pa[3]);
            *(uint4*)&A_s[sr * 40 + sc] = u0;
            *(uint4*)&A_s[sr * 40 + sc + 8] = u1;
            uint4 v0 = pack8(pb[0], pb[1]), v1 = pack8(pb[2], pb[3]);
            *(uint4*)&B_s[sr * 40 + sc] = v0;
            *(uint4*)&B_s[sr * 40 + sc + 8] = v1;
        }
        __syncthreads();
        if (kt + 1 < NKT) {
            const float* An = Ald + (kt + 1) * 32;
            const float* Bn = Bld + (kt + 1) * 32;
#pragma unroll
            for (int i = 0; i < 4; ++i) {
                pa[i] = *(const float4*)(An + 4 * i);
                pb[i] = *(const float4*)(Bn + 4 * i);
            }
        }
#pragma unroll
        for (int ks = 0; ks < 2; ++ks) {
            const int k0 = ks * 16;
            uint32_t a[2][4];
#pragma unroll
            for (int mt = 0; mt < 2; ++mt) {
                uint32_t ad = aBase +
                    (uint32_t)(((nrow + mt * 16 + mrow) * 40 + k0 + mck) * 2);
                ldm_x4(a[mt][0], a[mt][1], a[mt][2], a[mt][3], ad);
            }
            uint32_t b[8][2];
#pragma unroll
            for (int bt = 0; bt < 4; ++bt) {
                uint32_t r0, r1, r2, r3;
                uint32_t bd = bBase +
                    (uint32_t)(((mcol + bt * 16 + mrow) * 40 + k0 + mck) * 2);
                ldm_x4(r0, r1, r2, r3, bd);
                b[2 * bt][0] = r0; b[2 * bt + 1][0] = r1;
                b[2 * bt][1] = r2; b[2 * bt + 1][1] = r3;
            }
#pragma unroll
            for (int mt = 0; mt < 2; ++mt)
#pragma unroll
                for (int nt = 0; nt < 8; ++nt)
                    mma16816(c[mt][nt], a[mt], b[nt][0], b[nt][1]);
        }
    }

#pragma unroll
    for (int mt = 0; mt < 2; ++mt) {
        const int n = n0 + nrow + mt * 16 + (lane >> 2);
#pragma unroll
        for (int nt = 0; nt < 8; ++nt) {
            const int m = m0 + mcol + nt * 8 + (lane & 3) * 2;
            float2 bb = *(const float2*)(bias + m);
            float* cp = g_xp + (size_t)n * R4H + m;
            float2 o0, o1;
            o0.x = c[mt][nt][0] + bb.x; o0.y = c[mt][nt][1] + bb.y;
            o1.x = c[mt][nt][2] + bb.x; o1.y = c[mt][nt][3] + bb.y;
            *(float2*)cp = o0;
            *(float2*)(cp + (size_t)8 * R4H) = o1;
        }
    }
}

// ---------------------------------------------------------------- LSTM
// R16 inner loop verbatim; barrier region trimmed: one bar removed (epilogue
// warp-local), out-stores/xp-prefetch after arrive, nanosleep poll backoff.
__global__ void __launch_bounds__(NTH, 2)
lstm_kernel(const float* __restrict__ c0, const float* __restrict__ W_hh,
            const float* __restrict__ b_hh, float* __restrict__ out) {
    extern __shared__ __align__(16) unsigned char smem_raw[];
    uint4* Wq = reinterpret_cast<uint4*>(smem_raw);
    float* pre_part = reinterpret_cast<float*>(smem_raw + (size_t)ROWS * HV * 2);

    const int tid = threadIdx.x, cta = blockIdx.x;
    const int j0 = cta * JPC;
    int J = HV - j0; if (J > JPC) J = JPC; if (J < 0) J = 0;

    // stage W_hh slice -> SMEM fp16, vectorized (uint4 = 8 halves)
    for (int u = tid; u < ROWS * 256; u += NTH) {
        int rl = u >> 8, rem = u & 255;
        int jl = rl >> 2, gate = rl & 3;
        uint4 v = make_uint4(0, 0, 0, 0);
        if (jl < J) {
            const float* wp = W_hh + ((size_t)gate * HV + j0 + jl) * HV + rem * 8;
            v = pack8(*(const float4*)wp, *(const float4*)(wp + 4));
        }
        Wq[u] = v;
    }

    const int warp = tid >> 5, lane = tid & 31;
    const int grp = warp >> 1, khalf = warp & 1;
    const int kb = khalf << 10;
    const int rbase = grp * JPC;

    float c_val = 0.f, b_r[4] = {0.f, 0.f, 0.f, 0.f};
    if (tid < J) {
        c_val = c0[j0 + tid];
#pragma unroll
        for (int g = 0; g < 4; ++g) b_r[g] = b_hh[g * HV + j0 + tid];
    }
    float xp_r[4] = {0.f, 0.f, 0.f, 0.f};
    if (tid < J) {
#pragma unroll
        for (int g = 0; g < 4; ++g)
            xp_r[g] = __ldcg(&g_xp[(size_t)g * HV + j0 + tid]);
    }
    __syncthreads();

    const size_t wbase = (size_t)rbase * 256 + (size_t)khalf * 128 + lane;
    volatile unsigned int* barp = &g_bar;
    const __half2 hz = __float2half2_rn(0.f);

    for (int t = 0; t < STEPS; ++t) {
        const int p = t & 1;

        uint4 hq[4];
        {
            const uint4* hb4 = reinterpret_cast<const uint4*>(&g_hh[p][kb]) + lane;
#pragma unroll
            for (int it = 0; it < 4; ++it) hq[it] = __ldcg(hb4 + it * 32);
        }

        __half2 acc[JPC][4];
#pragma unroll
        for (int r = 0; r < JPC; ++r)
#pragma unroll
            for (int s = 0; s < 4; ++s) acc[r][s] = hz;

#pragma unroll
        for (int it = 0; it < 4; ++it) {
#pragma unroll
            for (int r = 0; r < JPC; ++r) {
                uint4 w = Wq[wbase + (size_t)r * 256 + it * 32];
                acc[r][0] = __hfma2(u2h(w.x), u2h(hq[it].x), acc[r][0]);
                acc[r][1] = __hfma2(u2h(w.y), u2h(hq[it].y), acc[r][1]);
                acc[r][2] = __hfma2(u2h(w.z), u2h(hq[it].z), acc[r][2]);
                acc[r][3] = __hfma2(u2h(w.w), u2h(hq[it].w), acc[r][3]);
            }
        }
#pragma unroll
        for (int r = 0; r < JPC; ++r) {
            float2 f0 = __half22float2(acc[r][0]);
            float2 f1 = __half22float2(acc[r][1]);
            float2 f2 = __half22float2(acc[r][2]);
            float2 f3 = __half22float2(acc[r][3]);
            float v = ((f0.x + f0.y) + (f1.x + f1.y)) +
                      ((f2.x + f2.y) + (f3.x + f3.y));
            v += __shfl_xor_sync(~0u, v, 16);
            v += __shfl_xor_sync(~0u, v, 8);
            v += __shfl_xor_sync(~0u, v, 4);
            v += __shfl_xor_sync(~0u, v, 2);
            v += __shfl_xor_sync(~0u, v, 1);
            if (lane == 0) pre_part[khalf * ROWS + rbase + r] = v;
        }
        __syncthreads();   // #1: pre_part ready for warp 0

        const unsigned tgt = (unsigned)(t + 1) * GRID;
        if (warp == 0) {
            float h_n = 0.f, f_t = 0.f, i_t = 0.f;
            if (tid < J) {
                const int rl = tid << 2;
                float pi = xp_r[0] + b_r[0] + pre_part[rl + 0] + pre_part[ROWS + rl + 0];
                float pf = xp_r[1] + b_r[1] + pre_part[rl + 1] + pre_part[ROWS + rl + 1];
                float po = xp_r[2] + b_r[2] + pre_part[rl + 2] + pre_part[ROWS + rl + 2];
                float pg = xp_r[3] + b_r[3] + pre_part[rl + 3] + pre_part[ROWS + rl + 3];
                i_t = __fdividef(1.0f, 1.0f + __expf(-pi));
                f_t = __fdividef(1.0f, 1.0f + __expf(-pf));
                float o_t = __fdividef(1.0f, 1.0f + __expf(-po));
                float g_t = __fdividef(2.0f, 1.0f + __expf(-2.0f * pg)) - 1.0f;
                c_val = c_val * f_t + i_t * g_t;
                float tc = __fdividef(2.0f, 1.0f + __expf(-2.0f * c_val)) - 1.0f;
                h_n = o_t * tc;
                g_hh[p ^ 1][j0 + tid] = __float2half(h_n);   // publish h first
            }
            __syncwarp();                 // warp-local: h stores visible to lane0
            if (lane == 0) {
                __threadfence();          // drain h store (warp-cumulative)
                atomicAdd(&g_bar, 1u);    // REDG arrive
            }
            if (tid < J) {                // off the critical path
                size_t oi = (size_t)t * HV + j0 + tid;
                out[oi] = h_n;
                out[OUTSTRIDE + oi] = f_t;
                out[2 * OUTSTRIDE + oi] = i_t;
                if (t + 1 < STEPS) {
#pragma unroll
                    for (int g = 0; g < 4; ++g)
                        xp_r[g] = __ldcg(&g_xp[(size_t)(t + 1) * R4H + g * HV + j0 + tid]);
                }
            }
        }
        // single spinner per CTA, nanosleep backoff (first poll immediate)
        if (tid == 0) {
            while (*barp < tgt) { __nanosleep(32); }
            __threadfence();
        }
        __syncthreads();   // #2: release all warps; fences pre_part reuse
    }
}

extern "C" void kernel_launch(void* const* d_in, const int* in_sizes, int n_in,
                              void* d_out, int out_size) {
    const float* input_ = (const float*)d_in[0];
    const float* h0 = (const float*)d_in[1];
    const float* c0 = (const float*)d_in[2];
    const float* W_ih = (const float*)d_in[3];
    const float* b_ih = (const float*)d_in[4];
    const float* W_hh = (const float*)d_in[5];
    const float* b_hh = (const float*)d_in[6];
    float* out = (float*)d_out;

    static int smem_set = 0;
    if (!smem_set) {
        cudaFuncSetAttribute(lstm_kernel, cudaFuncAttributeMaxDynamicSharedMemorySize,
                             LSTM_SMEM);
        smem_set = 1;
    }

    gemm_xp<<<dim3(R4H / 128, STEPS / 128), 256>>>(input_, W_ih, b_ih, h0);
    lstm_kernel<<<GRID, NTH, LSTM_SMEM>>>(c0, W_hh, b_hh, out);
}